// round 3
// baseline (speedup 1.0000x reference)
#include <cuda_runtime.h>
#include <cstdint>

// GptOssExperts: out[t,h] = sum_e r[t,e]*(act(hs@gup[e]+gub[e])@dp[e]+dpb[e])
// tcgen05 is rejected by this toolchain's PTX target (sm_103 base), so this uses the
// legacy mma.sync.m16n8k8 tf32 path, optimized:
//  - 128x256 CTA tile, 8 warps of 64x64 (acc 128 regs)
//  - SMEM holds tiles in *fragment layout*: A frags load as 1x LDS.128, B frags as 1x LDS.64,
//    conflict-free; no swizzle, no scalar gathers in the mainloop.
//  - double-buffered SMEM, register-staged global prefetch overlapping MMA.

constexpr int T_DIM = 2048, H_DIM = 2048, I_DIM = 2048, E_NUM = 8;
constexpr int GU_COLS = 4096;         // 2*I
constexpr int KQ = E_NUM * I_DIM;     // 16384
constexpr int BM = 128, BN = 256, BK = 16;

// dynamic SMEM layout
constexpr int OFF_A   = 0;            // 2 bufs x 8192  (16 frags x 32 lanes x 16B)
constexpr int OFF_B   = 16384;        // 2 bufs x 16384 (64 frags x 32 lanes x 8B)
constexpr int OFF_AUX = 49152;        // up to 12KB aux
constexpr int SMEM_SZ = 61440;

__device__ float g_inter[33554432];   // [T][E*I] routed-scaled intermediate (134 MB)

__device__ __forceinline__ uint32_t f2tf32(float x) {
    uint32_t r; asm("cvt.rna.tf32.f32 %0, %1;" : "=r"(r) : "f"(x)); return r;
}

__device__ __forceinline__ void mma_tf32(float (&c)[4],
    uint32_t a0, uint32_t a1, uint32_t a2, uint32_t a3, uint32_t b0, uint32_t b1)
{
    asm volatile(
        "mma.sync.aligned.m16n8k8.row.col.f32.tf32.tf32.f32 "
        "{%0,%1,%2,%3}, {%4,%5,%6,%7}, {%8,%9}, {%0,%1,%2,%3};"
        : "+f"(c[0]), "+f"(c[1]), "+f"(c[2]), "+f"(c[3])
        : "r"(a0), "r"(a1), "r"(a2), "r"(a3), "r"(b0), "r"(b1));
}

// Fragment layouts (per k8 step s):
//  A: frag f = s*8 + (m>>4); within frag: lane = (m&7)*4 + (k&3), reg = ((m>>3)&1) + 2*((k>>2)&1)
//     addr = f*512 + lane*16 + reg*4      -> compute side: one LDS.128 per frag
//  B: frag f = s*32 + (n>>3); within frag: lane = (n&7)*4 + (k&3), reg = (k>>2)&1
//     addr = f*256 + lane*8 + reg*4       -> compute side: one LDS.64 per frag

struct Writer {
    uint32_t a_st[2]; const float* a_ld[2];
    uint32_t b_st[4]; const float* b_ld[4];
};

__device__ __forceinline__ void init_writer(Writer& w,
    const float* __restrict__ A, int lda, const float* __restrict__ B, int ldb)
{
    const int tid = threadIdx.x;
#pragma unroll
    for (int j = 0; j < 2; j++) {               // A tile: 512 float4 (128 rows x 16 cols)
        int idx = tid + 256 * j;
        int m = idx >> 2, k0 = (idx & 3) << 2;  // 4 consecutive k -> 4 lanes, same reg
        int s = k0 >> 3, regk = (k0 >> 2) & 1;
        int mf = m >> 4, gg = m & 7, him = (m >> 3) & 1;
        w.a_st[j] = (uint32_t)(((s * 8 + mf) * 32 + gg * 4) * 16 + (him + 2 * regk) * 4);
        w.a_ld[j] = A + (size_t)m * lda + k0;
    }
#pragma unroll
    for (int j = 0; j < 4; j++) {               // B tile: 1024 float4 (16 rows x 256 cols)
        int idx = tid + 256 * j;
        int k = idx >> 6, n0 = (idx & 63) << 2; // 4 consecutive n -> 4 lanes, same reg
        int s = k >> 3, t4 = k & 3, regk = (k >> 2) & 1;
        int nf = n0 >> 3, g0 = n0 & 7;
        w.b_st[j] = (uint32_t)(((s * 32 + nf) * 32 + g0 * 4 + t4) * 8 + regk * 4);
        w.b_ld[j] = B + (size_t)k * ldb + n0;
    }
}

__device__ __forceinline__ void store_slab(char* ab, char* bb, const Writer& w,
    const float4 (&va)[2], const float4 (&vb)[4])
{
#pragma unroll
    for (int j = 0; j < 2; j++) {
        char* p = ab + w.a_st[j];
        *(uint32_t*)(p)      = f2tf32(va[j].x);
        *(uint32_t*)(p + 16) = f2tf32(va[j].y);
        *(uint32_t*)(p + 32) = f2tf32(va[j].z);
        *(uint32_t*)(p + 48) = f2tf32(va[j].w);
    }
#pragma unroll
    for (int j = 0; j < 4; j++) {
        char* p = bb + w.b_st[j];
        *(uint32_t*)(p)      = f2tf32(vb[j].x);
        *(uint32_t*)(p + 32) = f2tf32(vb[j].y);
        *(uint32_t*)(p + 64) = f2tf32(vb[j].z);
        *(uint32_t*)(p + 96) = f2tf32(vb[j].w);
    }
}

__device__ __forceinline__ void compute_slab(const char* ab, const char* bb,
    int wr, int wc, int lane, float (&acc)[4][8][4])
{
#pragma unroll
    for (int s = 0; s < 2; s++) {
        uint4 af[4]; uint2 bf[8];
#pragma unroll
        for (int mf = 0; mf < 4; mf++)
            af[mf] = *(const uint4*)(ab + (size_t)(s * 8 + wr * 4 + mf) * 512 + lane * 16);
#pragma unroll
        for (int nf = 0; nf < 8; nf++)
            bf[nf] = *(const uint2*)(bb + (size_t)(s * 32 + wc * 8 + nf) * 256 + lane * 8);
#pragma unroll
        for (int mf = 0; mf < 4; mf++)
#pragma unroll
            for (int nf = 0; nf < 8; nf++)
                mma_tf32(acc[mf][nf], af[mf].x, af[mf].y, af[mf].z, af[mf].w,
                         bf[nf].x, bf[nf].y);
    }
}

__device__ __forceinline__ void run_gemm(
    const float* __restrict__ A, int lda, const float* __restrict__ B, int ldb,
    int nslab, char* smem, float (&acc)[4][8][4])
{
    const int tid = threadIdx.x, lane = tid & 31, wid = tid >> 5;
    const int wr = wid >> 2, wc = wid & 3;

    Writer w; init_writer(w, A, lda, B, ldb);

    float4 va[2], vb[4];
#pragma unroll
    for (int j = 0; j < 2; j++) va[j] = *(const float4*)w.a_ld[j];
#pragma unroll
    for (int j = 0; j < 4; j++) vb[j] = *(const float4*)w.b_ld[j];
    store_slab(smem + OFF_A, smem + OFF_B, w, va, vb);
    __syncthreads();

    int buf = 0;
    for (int i = 1; i < nslab; i++) {
        // prefetch slab i (LDG latency hidden under compute of slab i-1)
#pragma unroll
        for (int j = 0; j < 2; j++) va[j] = *(const float4*)(w.a_ld[j] + (size_t)i * BK);
#pragma unroll
        for (int j = 0; j < 4; j++) vb[j] = *(const float4*)(w.b_ld[j] + (size_t)i * BK * ldb);
        compute_slab(smem + OFF_A + buf * 8192, smem + OFF_B + buf * 16384, wr, wc, lane, acc);
        const int nb = buf ^ 1;
        store_slab(smem + OFF_A + nb * 8192, smem + OFF_B + nb * 16384, w, va, vb);
        __syncthreads();
        buf = nb;
    }
    compute_slab(smem + OFF_A + buf * 8192, smem + OFF_B + buf * 16384, wr, wc, lane, acc);
}

// ================= Stage 1: gu = hs @ gup[e] + gub; GLU; fold routing -> g_inter =================
__global__ __launch_bounds__(256, 1) void k_gemm1(
    const float* __restrict__ hidden, const float* __restrict__ routing,
    const float* __restrict__ gup, const float* __restrict__ gub)
{
    extern __shared__ char smem[];
    const int tid = threadIdx.x, lane = tid & 31, wid = tid >> 5;
    const int wr = wid >> 2, wc = wid & 3, g = lane >> 2, t4 = lane & 3;
    const int e = blockIdx.z, t0 = blockIdx.y * BM, j0 = blockIdx.x * BN;

    float* rs   = (float*)(smem + OFF_AUX);        // [128]
    float* bias = (float*)(smem + OFF_AUX + 512);  // [256]
    if (tid < 128) rs[tid] = routing[(size_t)(t0 + tid) * E_NUM + e];
    bias[tid] = gub[(size_t)e * GU_COLS + j0 + tid];

    float acc[4][8][4] = {};
    run_gemm(hidden + (size_t)t0 * H_DIM, H_DIM,
             gup + (size_t)e * H_DIM * GU_COLS + j0, GU_COLS,
             H_DIM / BK, smem, acc);

#pragma unroll
    for (int mf = 0; mf < 4; mf++) {
#pragma unroll
        for (int hi = 0; hi < 2; hi++) {
            const int r = wr * 64 + mf * 16 + g + hi * 8;
            const float rv = rs[r];
            float* grow = g_inter + (size_t)(t0 + r) * KQ + (size_t)e * I_DIM + (j0 >> 1);
#pragma unroll
            for (int nf = 0; nf < 8; nf++) {
                const int cn = wc * 64 + nf * 8 + 2 * t4;  // even gu col = gate; +1 = up
                float gate = acc[mf][nf][hi * 2]     + bias[cn];
                float up   = acc[mf][nf][hi * 2 + 1] + bias[cn + 1];
                gate = fminf(gate, 7.0f);
                up   = fminf(fmaxf(up, -7.0f), 7.0f);
                const float glu = gate / (1.0f + __expf(-1.702f * gate));
                grow[cn >> 1] = (up + 1.0f) * glu * rv;
            }
        }
    }
}

// ================= Stage 2: out = inter'[T,E*I] @ down[E*I,H] + routing @ dpb =================
__global__ __launch_bounds__(256, 1) void k_gemm2(
    const float* __restrict__ routing, const float* __restrict__ down,
    const float* __restrict__ dpb, float* __restrict__ out)
{
    extern __shared__ char smem[];
    const int tid = threadIdx.x, lane = tid & 31, wid = tid >> 5;
    const int wr = wid >> 2, wc = wid & 3, g = lane >> 2, t4 = lane & 3;
    const int t0 = blockIdx.y * BM, h0 = blockIdx.x * BN;

    float* rsm = (float*)(smem + OFF_AUX);         // [128][8]
    float* dsm = (float*)(smem + OFF_AUX + 4096);  // [8][256]
#pragma unroll
    for (int j = 0; j < 4; j++) {
        int idx = tid + 256 * j;
        rsm[idx] = routing[(size_t)t0 * E_NUM + idx];
    }
#pragma unroll
    for (int j = 0; j < 8; j++) {
        int idx = tid + 256 * j;
        dsm[idx] = dpb[(size_t)(idx >> 8) * H_DIM + h0 + (idx & 255)];
    }

    float acc[4][8][4] = {};
    run_gemm(g_inter + (size_t)t0 * KQ, KQ,
             down + h0, H_DIM,
             KQ / BK, smem, acc);

#pragma unroll
    for (int nf = 0; nf < 8; nf++) {
        const int cn = wc * 64 + nf * 8 + 2 * t4;
        float d0[8], d1[8];
#pragma unroll
        for (int e2 = 0; e2 < 8; e2++) {
            d0[e2] = dsm[e2 * 256 + cn];
            d1[e2] = dsm[e2 * 256 + cn + 1];
        }
#pragma unroll
        for (int mf = 0; mf < 4; mf++) {
#pragma unroll
            for (int hi = 0; hi < 2; hi++) {
                const int r = wr * 64 + mf * 16 + g + hi * 8;
                const float4* rp = (const float4*)(rsm + r * 8);
                const float4 rA = rp[0], rB = rp[1];
                float b0 = rA.x * d0[0] + rA.y * d0[1] + rA.z * d0[2] + rA.w * d0[3]
                         + rB.x * d0[4] + rB.y * d0[5] + rB.z * d0[6] + rB.w * d0[7];
                float b1 = rA.x * d1[0] + rA.y * d1[1] + rA.z * d1[2] + rA.w * d1[3]
                         + rB.x * d1[4] + rB.y * d1[5] + rB.z * d1[6] + rB.w * d1[7];
                float2 v;
                v.x = acc[mf][nf][hi * 2]     + b0;
                v.y = acc[mf][nf][hi * 2 + 1] + b1;
                *(float2*)(out + (size_t)(t0 + r) * H_DIM + h0 + cn) = v;
            }
        }
    }
}

extern "C" void kernel_launch(void* const* d_in, const int* in_sizes, int n_in,
                              void* d_out, int out_size)
{
    const float* hidden  = (const float*)d_in[0];
    const float* routing = (const float*)d_in[1];
    const float* gup     = (const float*)d_in[2];
    const float* gub     = (const float*)d_in[3];
    const float* down    = (const float*)d_in[4];
    const float* dpb     = (const float*)d_in[5];
    float* out = (float*)d_out;

    cudaFuncSetAttribute(k_gemm1, cudaFuncAttributeMaxDynamicSharedMemorySize, SMEM_SZ);
    cudaFuncSetAttribute(k_gemm2, cudaFuncAttributeMaxDynamicSharedMemorySize, SMEM_SZ);

    dim3 g1(GU_COLS / BN, T_DIM / BM, E_NUM);   // (16, 16, 8)
    k_gemm1<<<g1, 256, SMEM_SZ>>>(hidden, routing, gup, gub);

    dim3 g2(H_DIM / BN, T_DIM / BM);            // (8, 16)
    k_gemm2<<<g2, 256, SMEM_SZ>>>(routing, down, dpb, out);
}

// round 4
// speedup vs baseline: 2.9864x; 2.9864x over previous
#include <cuda_runtime.h>
#include <cstdint>

// GptOssExperts: out[t,h] = sum_e r[t,e]*(act(hs@gup[e]+gub[e])@dp[e]+dpb[e])
// Legacy mma.sync tf32 path (tcgen05 rejected by toolchain's sm_103 base target).
//  - 128x256 CTA tile, 8 warps of 64x64  (halves mem-instr per MAC vs BN=128)
//  - cp.async.cg 4-stage pipeline, raw fp32 in smem, cvt.rna.tf32 at fragment load
//  - padded smem rows: A row=80B, B row=1056B -> all fragment LDS conflict-free

constexpr int T_DIM = 2048, H_DIM = 2048, I_DIM = 2048, E_NUM = 8;
constexpr int GU_COLS = 4096;          // 2*I
constexpr int KQ = E_NUM * I_DIM;      // 16384
constexpr int BM = 128, BN = 256, BK = 16;
constexpr int STAGES = 4;

constexpr int A_ROW = 80;              // 16 floats + 16B pad
constexpr int B_ROW = 1056;            // 256 floats + 32B pad
constexpr int A_ST = BM * A_ROW;       // 10240
constexpr int B_ST = BK * B_ROW;       // 16896
constexpr int OFF_A = 0;
constexpr int OFF_B = STAGES * A_ST;             // 40960
constexpr int OFF_AUX = OFF_B + STAGES * B_ST;   // 108544
constexpr int SMEM_SZ = OFF_AUX + 12544;         // ~118KB

__device__ float g_inter[33554432];    // [T][E*I] routed-scaled intermediate (134 MB)

__device__ __forceinline__ uint32_t f2tf32(float x) {
    uint32_t r; asm("cvt.rna.tf32.f32 %0, %1;" : "=r"(r) : "f"(x)); return r;
}
__device__ __forceinline__ uint32_t cvta_smem(const void* p) {
    uint32_t a;
    asm("{ .reg .u64 t; cvta.to.shared.u64 t, %1; cvt.u32.u64 %0, t; }" : "=r"(a) : "l"(p));
    return a;
}
__device__ __forceinline__ void cp16(uint32_t saddr, const void* g) {
    asm volatile("cp.async.cg.shared.global [%0], [%1], 16;" :: "r"(saddr), "l"(g));
}
__device__ __forceinline__ void cp_commit() {
    asm volatile("cp.async.commit_group;" ::);
}
template <int N> __device__ __forceinline__ void cp_wait() {
    asm volatile("cp.async.wait_group %0;" :: "n"(N));
}
__device__ __forceinline__ void mma_tf32(float (&c)[4],
    uint32_t a0, uint32_t a1, uint32_t a2, uint32_t a3, uint32_t b0, uint32_t b1)
{
    asm volatile(
        "mma.sync.aligned.m16n8k8.row.col.f32.tf32.tf32.f32 "
        "{%0,%1,%2,%3}, {%4,%5,%6,%7}, {%8,%9}, {%0,%1,%2,%3};"
        : "+f"(c[0]), "+f"(c[1]), "+f"(c[2]), "+f"(c[3])
        : "r"(a0), "r"(a1), "r"(a2), "r"(a3), "r"(b0), "r"(b1));
}

// ---- fragment compute on one BK=16 slab (two k=8 substeps) ----
// A frag bank: (20g + t4 + C)%32 distinct over warp -> conflict-free
// B frag bank: (8*t4 + g + C)%32 distinct over warp -> conflict-free
__device__ __forceinline__ void compute_slab(const char* sA, const char* sB,
    int wr, int wc, int g, int t4, float (&acc)[4][8][4])
{
#pragma unroll
    for (int s = 0; s < 2; s++) {
        const int koff = 2 * s * 16 + t4 * 4;      // (k>>2)*16 + (k&3)*4 for k=s*8+t4
        uint32_t a[4][4];
#pragma unroll
        for (int mf = 0; mf < 4; mf++) {
            const char* p0 = sA + (wr * 64 + mf * 16 + g) * A_ROW + koff;
            a[mf][0] = f2tf32(*(const float*)(p0));
            a[mf][1] = f2tf32(*(const float*)(p0 + 8 * A_ROW));
            a[mf][2] = f2tf32(*(const float*)(p0 + 16));          // k+4 -> next 16B quad
            a[mf][3] = f2tf32(*(const float*)(p0 + 8 * A_ROW + 16));
        }
        uint32_t b[8][2];
        const char* pb = sB + (s * 8 + t4) * B_ROW + (wc * 64 + g) * 4;
#pragma unroll
        for (int nf = 0; nf < 8; nf++) {
            b[nf][0] = f2tf32(*(const float*)(pb + nf * 32));
            b[nf][1] = f2tf32(*(const float*)(pb + nf * 32 + 4 * B_ROW));
        }
#pragma unroll
        for (int mf = 0; mf < 4; mf++)
#pragma unroll
            for (int nf = 0; nf < 8; nf++)
                mma_tf32(acc[mf][nf], a[mf][0], a[mf][1], a[mf][2], a[mf][3],
                         b[nf][0], b[nf][1]);
    }
}

// ---- cp.async copy of slab i into stage slot ----
struct Copier {
    const float* ga[2]; uint32_t sa[2];   // A: 2 x 16B chunks per thread
    const float* gb[4]; uint32_t sb[4];   // B: 4 x 16B chunks per thread
    int ldb;
};
__device__ __forceinline__ void init_copier(Copier& c, uint32_t smem_u32,
    const float* __restrict__ A, int lda, const float* __restrict__ B, int ldb)
{
    const int tid = threadIdx.x;
    c.ldb = ldb;
#pragma unroll
    for (int j = 0; j < 2; j++) {
        int idx = tid + 256 * j;
        int m = idx >> 2, kq = idx & 3;
        c.sa[j] = smem_u32 + OFF_A + m * A_ROW + kq * 16;
        c.ga[j] = A + (size_t)m * lda + kq * 4;
    }
#pragma unroll
    for (int j = 0; j < 4; j++) {
        int idx = tid + 256 * j;
        int k = idx >> 6, nq = idx & 63;
        c.sb[j] = smem_u32 + OFF_B + k * B_ROW + nq * 16;
        c.gb[j] = B + (size_t)k * ldb + nq * 4;
    }
}
__device__ __forceinline__ void issue_slab(const Copier& c, int i) {
    const int slot = i & (STAGES - 1);
    const size_t ka = (size_t)i * BK;
#pragma unroll
    for (int j = 0; j < 2; j++)
        cp16(c.sa[j] + slot * A_ST, c.ga[j] + ka);
#pragma unroll
    for (int j = 0; j < 4; j++)
        cp16(c.sb[j] + slot * B_ST, c.gb[j] + ka * c.ldb);
}

__device__ __forceinline__ void run_gemm(
    const float* __restrict__ A, int lda, const float* __restrict__ B, int ldb,
    int nslab, char* smem, uint32_t smem_u32, float (&acc)[4][8][4])
{
    const int tid = threadIdx.x, lane = tid & 31, wid = tid >> 5;
    const int wr = wid >> 2, wc = wid & 3, g = lane >> 2, t4 = lane & 3;

    Copier c; init_copier(c, smem_u32, A, lda, B, ldb);

#pragma unroll
    for (int i = 0; i < STAGES - 1; i++) { issue_slab(c, i); cp_commit(); }

    for (int i = 0; i < nslab; i++) {
        cp_wait<STAGES - 2>();      // own group for slab i retired
        __syncthreads();            // all threads' copies for slab i visible;
                                    // all warps done computing slab i-1
        if (i + STAGES - 1 < nslab) issue_slab(c, i + STAGES - 1);
        cp_commit();
        const int slot = i & (STAGES - 1);
        compute_slab(smem + OFF_A + slot * A_ST, smem + OFF_B + slot * B_ST,
                     wr, wc, g, t4, acc);
    }
}

// ================= Stage 1: gu = hs @ gup[e] + gub; GLU; fold routing -> g_inter =================
__global__ __launch_bounds__(256, 1) void k_gemm1(
    const float* __restrict__ hidden, const float* __restrict__ routing,
    const float* __restrict__ gup, const float* __restrict__ gub)
{
    extern __shared__ char smem[];
    const uint32_t sb = cvta_smem(smem);
    const int tid = threadIdx.x, lane = tid & 31, wid = tid >> 5;
    const int wr = wid >> 2, wc = wid & 3, g = lane >> 2, t4 = lane & 3;
    const int e = blockIdx.z, t0 = blockIdx.y * BM, j0 = blockIdx.x * BN;

    float* rs   = (float*)(smem + OFF_AUX);        // [128]
    float* bias = (float*)(smem + OFF_AUX + 512);  // [256]
    if (tid < 128) rs[tid] = routing[(size_t)(t0 + tid) * E_NUM + e];
    bias[tid] = gub[(size_t)e * GU_COLS + j0 + tid];
    __syncthreads();

    float acc[4][8][4] = {};
    run_gemm(hidden + (size_t)t0 * H_DIM, H_DIM,
             gup + (size_t)e * H_DIM * GU_COLS + j0, GU_COLS,
             H_DIM / BK, smem, sb, acc);

#pragma unroll
    for (int mf = 0; mf < 4; mf++) {
#pragma unroll
        for (int hi = 0; hi < 2; hi++) {
            const int r = wr * 64 + mf * 16 + g + hi * 8;
            const float rv = rs[r];
            float* grow = g_inter + (size_t)(t0 + r) * KQ + (size_t)e * I_DIM + (j0 >> 1);
#pragma unroll
            for (int nf = 0; nf < 8; nf++) {
                const int cn = wc * 64 + nf * 8 + 2 * t4;  // even gu col = gate; +1 = up
                float gate = acc[mf][nf][hi * 2]     + bias[cn];
                float up   = acc[mf][nf][hi * 2 + 1] + bias[cn + 1];
                gate = fminf(gate, 7.0f);
                up   = fminf(fmaxf(up, -7.0f), 7.0f);
                const float glu = gate / (1.0f + __expf(-1.702f * gate));
                grow[cn >> 1] = (up + 1.0f) * glu * rv;
            }
        }
    }
}

// ================= Stage 2: out = inter'[T,E*I] @ down[E*I,H] + routing @ dpb =================
__global__ __launch_bounds__(256, 1) void k_gemm2(
    const float* __restrict__ routing, const float* __restrict__ down,
    const float* __restrict__ dpb, float* __restrict__ out)
{
    extern __shared__ char smem[];
    const uint32_t sb = cvta_smem(smem);
    const int tid = threadIdx.x, lane = tid & 31, wid = tid >> 5;
    const int wr = wid >> 2, wc = wid & 3, g = lane >> 2, t4 = lane & 3;
    const int t0 = blockIdx.y * BM, h0 = blockIdx.x * BN;

    float* rsm = (float*)(smem + OFF_AUX);         // [128][8]
    float* dsm = (float*)(smem + OFF_AUX + 4096);  // [8][256]
#pragma unroll
    for (int j = 0; j < 4; j++) {
        int idx = tid + 256 * j;
        rsm[idx] = routing[(size_t)t0 * E_NUM + idx];
    }
#pragma unroll
    for (int j = 0; j < 8; j++) {
        int idx = tid + 256 * j;
        dsm[idx] = dpb[(size_t)(idx >> 8) * H_DIM + h0 + (idx & 255)];
    }
    __syncthreads();

    float acc[4][8][4] = {};
    run_gemm(g_inter + (size_t)t0 * KQ, KQ,
             down + h0, H_DIM,
             KQ / BK, smem, sb, acc);

#pragma unroll
    for (int nf = 0; nf < 8; nf++) {
        const int cn = wc * 64 + nf * 8 + 2 * t4;
        float d0[8], d1[8];
#pragma unroll
        for (int e2 = 0; e2 < 8; e2++) {
            d0[e2] = dsm[e2 * 256 + cn];
            d1[e2] = dsm[e2 * 256 + cn + 1];
        }
#pragma unroll
        for (int mf = 0; mf < 4; mf++) {
#pragma unroll
            for (int hi = 0; hi < 2; hi++) {
                const int r = wr * 64 + mf * 16 + g + hi * 8;
                const float4* rp = (const float4*)(rsm + r * 8);
                const float4 rA = rp[0], rB = rp[1];
                float b0 = rA.x * d0[0] + rA.y * d0[1] + rA.z * d0[2] + rA.w * d0[3]
                         + rB.x * d0[4] + rB.y * d0[5] + rB.z * d0[6] + rB.w * d0[7];
                float b1 = rA.x * d1[0] + rA.y * d1[1] + rA.z * d1[2] + rA.w * d1[3]
                         + rB.x * d1[4] + rB.y * d1[5] + rB.z * d1[6] + rB.w * d1[7];
                float2 v;
                v.x = acc[mf][nf][hi * 2]     + b0;
                v.y = acc[mf][nf][hi * 2 + 1] + b1;
                *(float2*)(out + (size_t)(t0 + r) * H_DIM + h0 + cn) = v;
            }
        }
    }
}

extern "C" void kernel_launch(void* const* d_in, const int* in_sizes, int n_in,
                              void* d_out, int out_size)
{
    const float* hidden  = (const float*)d_in[0];
    const float* routing = (const float*)d_in[1];
    const float* gup     = (const float*)d_in[2];
    const float* gub     = (const float*)d_in[3];
    const float* down    = (const float*)d_in[4];
    const float* dpb     = (const float*)d_in[5];
    float* out = (float*)d_out;

    cudaFuncSetAttribute(k_gemm1, cudaFuncAttributeMaxDynamicSharedMemorySize, SMEM_SZ);
    cudaFuncSetAttribute(k_gemm2, cudaFuncAttributeMaxDynamicSharedMemorySize, SMEM_SZ);

    dim3 g1(GU_COLS / BN, T_DIM / BM, E_NUM);   // (16, 16, 8)
    k_gemm1<<<g1, 256, SMEM_SZ>>>(hidden, routing, gup, gub);

    dim3 g2(H_DIM / BN, T_DIM / BM);            // (8, 16)
    k_gemm2<<<g2, 256, SMEM_SZ>>>(routing, down, dpb, out);
}

// round 5
// speedup vs baseline: 3.1332x; 1.0492x over previous
#include <cuda_runtime.h>
#include <cstdint>

// GptOssExperts: out[t,h] = sum_e r[t,e]*(act(hs@gup[e]+gub[e])@dp[e]+dpb[e])
// Legacy mma.sync tf32 path (tcgen05 rejected by toolchain's sm_103 base target).
//  R5: BK=32 slabs (halve per-slab sync/wait/chain-restart overhead), 3-stage cp.async,
//      128x256 CTA / 64x64 warp tiles, padded conflict-free fragment loads.

constexpr int T_DIM = 2048, H_DIM = 2048, I_DIM = 2048, E_NUM = 8;
constexpr int GU_COLS = 4096;          // 2*I
constexpr int KQ = E_NUM * I_DIM;      // 16384
constexpr int BM = 128, BN = 256, BK = 32;
constexpr int STAGES = 3;

constexpr int A_ROW = 144;             // 32 floats + 16B pad  (bank stride 36)
constexpr int B_ROW = 1056;            // 256 floats + 32B pad (bank stride 264)
constexpr int A_ST = BM * A_ROW;       // 18432
constexpr int B_ST = BK * B_ROW;       // 33792
constexpr int OFF_A = 0;
constexpr int OFF_B = STAGES * A_ST;             // 55296
constexpr int OFF_AUX = OFF_B + STAGES * B_ST;   // 156672
constexpr int SMEM_SZ = OFF_AUX + 12544;         // 169216

__device__ float g_inter[33554432];    // [T][E*I] routed-scaled intermediate (134 MB)

__device__ __forceinline__ uint32_t f2tf32(float x) {
    uint32_t r; asm("cvt.rna.tf32.f32 %0, %1;" : "=r"(r) : "f"(x)); return r;
}
__device__ __forceinline__ uint32_t cvta_smem(const void* p) {
    uint32_t a;
    asm("{ .reg .u64 t; cvta.to.shared.u64 t, %1; cvt.u32.u64 %0, t; }" : "=r"(a) : "l"(p));
    return a;
}
__device__ __forceinline__ void cp16(uint32_t saddr, const void* g) {
    asm volatile("cp.async.cg.shared.global [%0], [%1], 16;" :: "r"(saddr), "l"(g));
}
__device__ __forceinline__ void cp_commit() {
    asm volatile("cp.async.commit_group;" ::);
}
template <int N> __device__ __forceinline__ void cp_wait() {
    asm volatile("cp.async.wait_group %0;" :: "n"(N));
}
__device__ __forceinline__ void mma_tf32(float (&c)[4],
    uint32_t a0, uint32_t a1, uint32_t a2, uint32_t a3, uint32_t b0, uint32_t b1)
{
    asm volatile(
        "mma.sync.aligned.m16n8k8.row.col.f32.tf32.tf32.f32 "
        "{%0,%1,%2,%3}, {%4,%5,%6,%7}, {%8,%9}, {%0,%1,%2,%3};"
        : "+f"(c[0]), "+f"(c[1]), "+f"(c[2]), "+f"(c[3])
        : "r"(a0), "r"(a1), "r"(a2), "r"(a3), "r"(b0), "r"(b1));
}

// ---- one BK=32 slab: 4 k8-steps, fully unrolled; loads of step s+1 overlap MMAs of s ----
// A element (m,k) at byte m*144 + k*4 ; frag bank = (4g + t4 + C)%32  -> conflict-free
// B element (k,n) at byte k*1056 + n*4; frag bank = (8t4 + g + C)%32  -> conflict-free
__device__ __forceinline__ void compute_slab(const char* sA, const char* sB,
    int wr, int wc, int g, int t4, float (&acc)[4][8][4])
{
#pragma unroll
    for (int s = 0; s < 4; s++) {
        const int k0 = s * 8 + t4;
        uint32_t a[4][4];
#pragma unroll
        for (int mf = 0; mf < 4; mf++) {
            const char* p0 = sA + (wr * 64 + mf * 16 + g) * A_ROW + k0 * 4;
            a[mf][0] = f2tf32(*(const float*)(p0));
            a[mf][1] = f2tf32(*(const float*)(p0 + 8 * A_ROW));
            a[mf][2] = f2tf32(*(const float*)(p0 + 16));            // k0 + 4
            a[mf][3] = f2tf32(*(const float*)(p0 + 8 * A_ROW + 16));
        }
        uint32_t b[8][2];
        const char* pb = sB + k0 * B_ROW + (wc * 64 + g) * 4;
#pragma unroll
        for (int nf = 0; nf < 8; nf++) {
            b[nf][0] = f2tf32(*(const float*)(pb + nf * 32));
            b[nf][1] = f2tf32(*(const float*)(pb + nf * 32 + 4 * B_ROW));
        }
#pragma unroll
        for (int mf = 0; mf < 4; mf++)
#pragma unroll
            for (int nf = 0; nf < 8; nf++)
                mma_tf32(acc[mf][nf], a[mf][0], a[mf][1], a[mf][2], a[mf][3],
                         b[nf][0], b[nf][1]);
    }
}

// ---- cp.async copy of one BK=32 slab ----
struct Copier {
    const float* ga[4]; uint32_t sa[4];   // A: 128x32 fl = 1024 chunks / 256 thr
    const float* gb[8]; uint32_t sb[8];   // B: 32x256 fl = 2048 chunks / 256 thr
    int ldb;
};
__device__ __forceinline__ void init_copier(Copier& c, uint32_t smem_u32,
    const float* __restrict__ A, int lda, const float* __restrict__ B, int ldb)
{
    const int tid = threadIdx.x;
    c.ldb = ldb;
#pragma unroll
    for (int j = 0; j < 4; j++) {
        int idx = tid + 256 * j;
        int m = idx >> 3, kq = idx & 7;
        c.sa[j] = smem_u32 + OFF_A + m * A_ROW + kq * 16;
        c.ga[j] = A + (size_t)m * lda + kq * 4;
    }
#pragma unroll
    for (int j = 0; j < 8; j++) {
        int idx = tid + 256 * j;
        int k = idx >> 6, nq = idx & 63;
        c.sb[j] = smem_u32 + OFF_B + k * B_ROW + nq * 16;
        c.gb[j] = B + (size_t)k * ldb + nq * 4;
    }
}
__device__ __forceinline__ void issue_slab(const Copier& c, int i) {
    const int slot = i % STAGES;
    const size_t ka = (size_t)i * BK;
#pragma unroll
    for (int j = 0; j < 4; j++)
        cp16(c.sa[j] + slot * A_ST, c.ga[j] + ka);
#pragma unroll
    for (int j = 0; j < 8; j++)
        cp16(c.sb[j] + slot * B_ST, c.gb[j] + ka * c.ldb);
}

__device__ __forceinline__ void run_gemm(
    const float* __restrict__ A, int lda, const float* __restrict__ B, int ldb,
    int nslab, char* smem, uint32_t smem_u32, float (&acc)[4][8][4])
{
    const int tid = threadIdx.x, lane = tid & 31, wid = tid >> 5;
    const int wr = wid >> 2, wc = wid & 3, g = lane >> 2, t4 = lane & 3;

    Copier c; init_copier(c, smem_u32, A, lda, B, ldb);

#pragma unroll
    for (int i = 0; i < STAGES - 1; i++) { issue_slab(c, i); cp_commit(); }

    for (int i = 0; i < nslab; i++) {
        cp_wait<STAGES - 2>();      // copies for slab i retired (this thread)
        __syncthreads();            // visible to all; all warps done with slot being refilled
        if (i + STAGES - 1 < nslab) issue_slab(c, i + STAGES - 1);
        cp_commit();
        const int slot = i % STAGES;
        compute_slab(smem + OFF_A + slot * A_ST, smem + OFF_B + slot * B_ST,
                     wr, wc, g, t4, acc);
    }
}

// ================= Stage 1: gu = hs @ gup[e] + gub; GLU; fold routing -> g_inter =================
__global__ __launch_bounds__(256, 1) void k_gemm1(
    const float* __restrict__ hidden, const float* __restrict__ routing,
    const float* __restrict__ gup, const float* __restrict__ gub)
{
    extern __shared__ char smem[];
    const uint32_t sb = cvta_smem(smem);
    const int tid = threadIdx.x, lane = tid & 31, wid = tid >> 5;
    const int wr = wid >> 2, wc = wid & 3, g = lane >> 2, t4 = lane & 3;
    const int e = blockIdx.z, t0 = blockIdx.y * BM, j0 = blockIdx.x * BN;

    float* rs   = (float*)(smem + OFF_AUX);        // [128]
    float* bias = (float*)(smem + OFF_AUX + 512);  // [256]
    if (tid < 128) rs[tid] = routing[(size_t)(t0 + tid) * E_NUM + e];
    bias[tid] = gub[(size_t)e * GU_COLS + j0 + tid];
    __syncthreads();

    float acc[4][8][4] = {};
    run_gemm(hidden + (size_t)t0 * H_DIM, H_DIM,
             gup + (size_t)e * H_DIM * GU_COLS + j0, GU_COLS,
             H_DIM / BK, smem, sb, acc);

#pragma unroll
    for (int mf = 0; mf < 4; mf++) {
#pragma unroll
        for (int hi = 0; hi < 2; hi++) {
            const int r = wr * 64 + mf * 16 + g + hi * 8;
            const float rv = rs[r];
            float* grow = g_inter + (size_t)(t0 + r) * KQ + (size_t)e * I_DIM + (j0 >> 1);
#pragma unroll
            for (int nf = 0; nf < 8; nf++) {
                const int cn = wc * 64 + nf * 8 + 2 * t4;  // even gu col = gate; +1 = up
                float gate = acc[mf][nf][hi * 2]     + bias[cn];
                float up   = acc[mf][nf][hi * 2 + 1] + bias[cn + 1];
                gate = fminf(gate, 7.0f);
                up   = fminf(fmaxf(up, -7.0f), 7.0f);
                const float glu = gate / (1.0f + __expf(-1.702f * gate));
                grow[cn >> 1] = (up + 1.0f) * glu * rv;
            }
        }
    }
}

// ================= Stage 2: out = inter'[T,E*I] @ down[E*I,H] + routing @ dpb =================
__global__ __launch_bounds__(256, 1) void k_gemm2(
    const float* __restrict__ routing, const float* __restrict__ down,
    const float* __restrict__ dpb, float* __restrict__ out)
{
    extern __shared__ char smem[];
    const uint32_t sb = cvta_smem(smem);
    const int tid = threadIdx.x, lane = tid & 31, wid = tid >> 5;
    const int wr = wid >> 2, wc = wid & 3, g = lane >> 2, t4 = lane & 3;
    const int t0 = blockIdx.y * BM, h0 = blockIdx.x * BN;

    float* rsm = (float*)(smem + OFF_AUX);         // [128][8]
    float* dsm = (float*)(smem + OFF_AUX + 4096);  // [8][256]
#pragma unroll
    for (int j = 0; j < 4; j++) {
        int idx = tid + 256 * j;
        rsm[idx] = routing[(size_t)t0 * E_NUM + idx];
    }
#pragma unroll
    for (int j = 0; j < 8; j++) {
        int idx = tid + 256 * j;
        dsm[idx] = dpb[(size_t)(idx >> 8) * H_DIM + h0 + (idx & 255)];
    }
    __syncthreads();

    float acc[4][8][4] = {};
    run_gemm(g_inter + (size_t)t0 * KQ, KQ,
             down + h0, H_DIM,
             KQ / BK, smem, sb, acc);

#pragma unroll
    for (int nf = 0; nf < 8; nf++) {
        const int cn = wc * 64 + nf * 8 + 2 * t4;
        float d0[8], d1[8];
#pragma unroll
        for (int e2 = 0; e2 < 8; e2++) {
            d0[e2] = dsm[e2 * 256 + cn];
            d1[e2] = dsm[e2 * 256 + cn + 1];
        }
#pragma unroll
        for (int mf = 0; mf < 4; mf++) {
#pragma unroll
            for (int hi = 0; hi < 2; hi++) {
                const int r = wr * 64 + mf * 16 + g + hi * 8;
                const float4* rp = (const float4*)(rsm + r * 8);
                const float4 rA = rp[0], rB = rp[1];
                float b0 = rA.x * d0[0] + rA.y * d0[1] + rA.z * d0[2] + rA.w * d0[3]
                         + rB.x * d0[4] + rB.y * d0[5] + rB.z * d0[6] + rB.w * d0[7];
                float b1 = rA.x * d1[0] + rA.y * d1[1] + rA.z * d1[2] + rA.w * d1[3]
                         + rB.x * d1[4] + rB.y * d1[5] + rB.z * d1[6] + rB.w * d1[7];
                float2 v;
                v.x = acc[mf][nf][hi * 2]     + b0;
                v.y = acc[mf][nf][hi * 2 + 1] + b1;
                *(float2*)(out + (size_t)(t0 + r) * H_DIM + h0 + cn) = v;
            }
        }
    }
}

extern "C" void kernel_launch(void* const* d_in, const int* in_sizes, int n_in,
                              void* d_out, int out_size)
{
    const float* hidden  = (const float*)d_in[0];
    const float* routing = (const float*)d_in[1];
    const float* gup     = (const float*)d_in[2];
    const float* gub     = (const float*)d_in[3];
    const float* down    = (const float*)d_in[4];
    const float* dpb     = (const float*)d_in[5];
    float* out = (float*)d_out;

    cudaFuncSetAttribute(k_gemm1, cudaFuncAttributeMaxDynamicSharedMemorySize, SMEM_SZ);
    cudaFuncSetAttribute(k_gemm2, cudaFuncAttributeMaxDynamicSharedMemorySize, SMEM_SZ);

    dim3 g1(GU_COLS / BN, T_DIM / BM, E_NUM);   // (16, 16, 8)
    k_gemm1<<<g1, 256, SMEM_SZ>>>(hidden, routing, gup, gub);

    dim3 g2(H_DIM / BN, T_DIM / BM);            // (8, 16)
    k_gemm2<<<g2, 256, SMEM_SZ>>>(routing, down, dpb, out);
}

// round 6
// speedup vs baseline: 3.2097x; 1.0244x over previous
#include <cuda_runtime.h>
#include <cstdint>

// GptOssExperts: out[t,h] = sum_e r[t,e]*(act(hs@gup[e]+gub[e])@dp[e]+dpb[e])
// Legacy mma.sync tf32 path (tcgen05 rejected by toolchain's sm_103 base target).
//  R6: 512 threads / 16 warps (4 per SMSP for latency hiding), 32x64 warp tiles;
//      all operands pre-rounded to tf32 in pre-pass kernels -> NO in-loop CVT;
//      BK=32, 3-stage cp.async, padded conflict-free fragment loads.

constexpr int T_DIM = 2048, H_DIM = 2048, I_DIM = 2048, E_NUM = 8;
constexpr int GU_COLS = 4096;          // 2*I
constexpr int KQ = E_NUM * I_DIM;      // 16384
constexpr int BM = 128, BN = 256, BK = 32;
constexpr int NTHR = 512;
constexpr int STAGES = 3;

constexpr int A_ROW = 144;             // 32 floats + 16B pad  (bank stride 36)
constexpr int B_ROW = 1056;            // 256 floats + 32B pad (bank stride 264)
constexpr int A_ST = BM * A_ROW;       // 18432
constexpr int B_ST = BK * B_ROW;       // 33792
constexpr int OFF_A = 0;
constexpr int OFF_B = STAGES * A_ST;             // 55296
constexpr int OFF_AUX = OFF_B + STAGES * B_ST;   // 156672
constexpr int SMEM_SZ = OFF_AUX + 12544;         // 169216

// static scratch (device-global; allocation-free)
__device__ float g_w1[67108864];       // tf32-rounded gate_up_proj  (268 MB)
__device__ float g_w2[33554432];       // tf32-rounded down_proj     (134 MB)
__device__ float g_hs[4194304];        // tf32-rounded hidden_states (16 MB)
__device__ float g_inter[33554432];    // routed-scaled intermediate [T][E*I], tf32-rounded

__device__ __forceinline__ uint32_t f2tf32(float x) {
    uint32_t r; asm("cvt.rna.tf32.f32 %0, %1;" : "=r"(r) : "f"(x)); return r;
}
__device__ __forceinline__ uint32_t cvta_smem(const void* p) {
    uint32_t a;
    asm("{ .reg .u64 t; cvta.to.shared.u64 t, %1; cvt.u32.u64 %0, t; }" : "=r"(a) : "l"(p));
    return a;
}
__device__ __forceinline__ void cp16(uint32_t saddr, const void* g) {
    asm volatile("cp.async.cg.shared.global [%0], [%1], 16;" :: "r"(saddr), "l"(g));
}
__device__ __forceinline__ void cp_commit() {
    asm volatile("cp.async.commit_group;" ::);
}
template <int N> __device__ __forceinline__ void cp_wait() {
    asm volatile("cp.async.wait_group %0;" :: "n"(N));
}
__device__ __forceinline__ void mma_tf32(float (&c)[4],
    uint32_t a0, uint32_t a1, uint32_t a2, uint32_t a3, uint32_t b0, uint32_t b1)
{
    asm volatile(
        "mma.sync.aligned.m16n8k8.row.col.f32.tf32.tf32.f32 "
        "{%0,%1,%2,%3}, {%4,%5,%6,%7}, {%8,%9}, {%0,%1,%2,%3};"
        : "+f"(c[0]), "+f"(c[1]), "+f"(c[2]), "+f"(c[3])
        : "r"(a0), "r"(a1), "r"(a2), "r"(a3), "r"(b0), "r"(b1));
}

// ---- pre-pass: round fp32 -> tf32-representable fp32 (vectorized) ----
__global__ __launch_bounds__(256) void k_conv(const float4* __restrict__ src,
                                              float4* __restrict__ dst, int n4)
{
    int i = blockIdx.x * 256 + threadIdx.x;
    if (i < n4) {
        float4 v = src[i];
        float4 o;
        o.x = __uint_as_float(f2tf32(v.x));
        o.y = __uint_as_float(f2tf32(v.y));
        o.z = __uint_as_float(f2tf32(v.z));
        o.w = __uint_as_float(f2tf32(v.w));
        dst[i] = o;
    }
}

// ---- one BK=32 slab: 4 k8-steps, raw LDS bits straight into MMA (no CVT) ----
// A element (m,k) at byte m*144 + k*4 ; frag bank = (4g + t4 + C)%32  -> conflict-free
// B element (k,n) at byte k*1056 + n*4; frag bank = (8t4 + g + C)%32  -> conflict-free
__device__ __forceinline__ void compute_slab(const char* sA, const char* sB,
    int wr, int wc, int g, int t4, float (&acc)[2][8][4])
{
#pragma unroll
    for (int s = 0; s < 4; s++) {
        const int k0 = s * 8 + t4;
        uint32_t a[2][4];
#pragma unroll
        for (int mf = 0; mf < 2; mf++) {
            const char* p0 = sA + (wr * 32 + mf * 16 + g) * A_ROW + k0 * 4;
            a[mf][0] = *(const uint32_t*)(p0);
            a[mf][1] = *(const uint32_t*)(p0 + 8 * A_ROW);
            a[mf][2] = *(const uint32_t*)(p0 + 16);             // k0 + 4
            a[mf][3] = *(const uint32_t*)(p0 + 8 * A_ROW + 16);
        }
        uint32_t b[8][2];
        const char* pb = sB + k0 * B_ROW + (wc * 64 + g) * 4;
#pragma unroll
        for (int nf = 0; nf < 8; nf++) {
            b[nf][0] = *(const uint32_t*)(pb + nf * 32);
            b[nf][1] = *(const uint32_t*)(pb + nf * 32 + 4 * B_ROW);
        }
#pragma unroll
        for (int mf = 0; mf < 2; mf++)
#pragma unroll
            for (int nf = 0; nf < 8; nf++)
                mma_tf32(acc[mf][nf], a[mf][0], a[mf][1], a[mf][2], a[mf][3],
                         b[nf][0], b[nf][1]);
    }
}

// ---- cp.async copy of one BK=32 slab (512 threads) ----
struct Copier {
    const float* ga[2]; uint32_t sa[2];   // A: 1024 chunks / 512 thr
    const float* gb[4]; uint32_t sb[4];   // B: 2048 chunks / 512 thr
    int ldb;
};
__device__ __forceinline__ void init_copier(Copier& c, uint32_t smem_u32,
    const float* __restrict__ A, int lda, const float* __restrict__ B, int ldb)
{
    const int tid = threadIdx.x;
    c.ldb = ldb;
#pragma unroll
    for (int j = 0; j < 2; j++) {
        int idx = tid + NTHR * j;
        int m = idx >> 3, kq = idx & 7;
        c.sa[j] = smem_u32 + OFF_A + m * A_ROW + kq * 16;
        c.ga[j] = A + (size_t)m * lda + kq * 4;
    }
#pragma unroll
    for (int j = 0; j < 4; j++) {
        int idx = tid + NTHR * j;
        int k = idx >> 6, nq = idx & 63;
        c.sb[j] = smem_u32 + OFF_B + k * B_ROW + nq * 16;
        c.gb[j] = B + (size_t)k * ldb + nq * 4;
    }
}
__device__ __forceinline__ void issue_slab(const Copier& c, int i) {
    const int slot = i % STAGES;
    const size_t ka = (size_t)i * BK;
#pragma unroll
    for (int j = 0; j < 2; j++)
        cp16(c.sa[j] + slot * A_ST, c.ga[j] + ka);
#pragma unroll
    for (int j = 0; j < 4; j++)
        cp16(c.sb[j] + slot * B_ST, c.gb[j] + ka * c.ldb);
}

__device__ __forceinline__ void run_gemm(
    const float* __restrict__ A, int lda, const float* __restrict__ B, int ldb,
    int nslab, char* smem, uint32_t smem_u32, float (&acc)[2][8][4])
{
    const int tid = threadIdx.x, lane = tid & 31, wid = tid >> 5;
    const int wr = wid >> 2, wc = wid & 3, g = lane >> 2, t4 = lane & 3;

    Copier c; init_copier(c, smem_u32, A, lda, B, ldb);

#pragma unroll
    for (int i = 0; i < STAGES - 1; i++) { issue_slab(c, i); cp_commit(); }

    for (int i = 0; i < nslab; i++) {
        cp_wait<STAGES - 2>();      // copies for slab i retired (this thread)
        __syncthreads();            // visible to all; all warps done with slot being refilled
        if (i + STAGES - 1 < nslab) issue_slab(c, i + STAGES - 1);
        cp_commit();
        const int slot = i % STAGES;
        compute_slab(smem + OFF_A + slot * A_ST, smem + OFF_B + slot * B_ST,
                     wr, wc, g, t4, acc);
    }
}

// ================= Stage 1: gu = hs @ gup[e] + gub; GLU; fold routing -> g_inter =================
__global__ __launch_bounds__(NTHR, 1) void k_gemm1(
    const float* __restrict__ routing, const float* __restrict__ gub)
{
    extern __shared__ char smem[];
    const uint32_t sb = cvta_smem(smem);
    const int tid = threadIdx.x, lane = tid & 31, wid = tid >> 5;
    const int wr = wid >> 2, wc = wid & 3, g = lane >> 2, t4 = lane & 3;
    const int e = blockIdx.z, t0 = blockIdx.y * BM, j0 = blockIdx.x * BN;

    float* rs   = (float*)(smem + OFF_AUX);        // [128]
    float* bias = (float*)(smem + OFF_AUX + 512);  // [256]
    if (tid < 128) rs[tid] = routing[(size_t)(t0 + tid) * E_NUM + e];
    if (tid < 256) bias[tid] = gub[(size_t)e * GU_COLS + j0 + tid];
    __syncthreads();

    float acc[2][8][4] = {};
    run_gemm(g_hs + (size_t)t0 * H_DIM, H_DIM,
             g_w1 + (size_t)e * H_DIM * GU_COLS + j0, GU_COLS,
             H_DIM / BK, smem, sb, acc);

#pragma unroll
    for (int mf = 0; mf < 2; mf++) {
#pragma unroll
        for (int hi = 0; hi < 2; hi++) {
            const int r = wr * 32 + mf * 16 + g + hi * 8;
            const float rv = rs[r];
            float* grow = g_inter + (size_t)(t0 + r) * KQ + (size_t)e * I_DIM + (j0 >> 1);
#pragma unroll
            for (int nf = 0; nf < 8; nf++) {
                const int cn = wc * 64 + nf * 8 + 2 * t4;  // even gu col = gate; +1 = up
                float gate = acc[mf][nf][hi * 2]     + bias[cn];
                float up   = acc[mf][nf][hi * 2 + 1] + bias[cn + 1];
                gate = fminf(gate, 7.0f);
                up   = fminf(fmaxf(up, -7.0f), 7.0f);
                const float glu = gate / (1.0f + __expf(-1.702f * gate));
                grow[cn >> 1] = __uint_as_float(f2tf32((up + 1.0f) * glu * rv));
            }
        }
    }
}

// ================= Stage 2: out = inter'[T,E*I] @ down[E*I,H] + routing @ dpb =================
__global__ __launch_bounds__(NTHR, 1) void k_gemm2(
    const float* __restrict__ routing, const float* __restrict__ dpb,
    float* __restrict__ out)
{
    extern __shared__ char smem[];
    const uint32_t sb = cvta_smem(smem);
    const int tid = threadIdx.x, lane = tid & 31, wid = tid >> 5;
    const int wr = wid >> 2, wc = wid & 3, g = lane >> 2, t4 = lane & 3;
    const int t0 = blockIdx.y * BM, h0 = blockIdx.x * BN;

    float* rsm = (float*)(smem + OFF_AUX);         // [128][8]
    float* dsm = (float*)(smem + OFF_AUX + 4096);  // [8][256]
#pragma unroll
    for (int j = 0; j < 2; j++) {
        int idx = tid + NTHR * j;
        rsm[idx] = routing[(size_t)t0 * E_NUM + idx];
    }
#pragma unroll
    for (int j = 0; j < 4; j++) {
        int idx = tid + NTHR * j;
        dsm[idx] = dpb[(size_t)(idx >> 8) * H_DIM + h0 + (idx & 255)];
    }
    __syncthreads();

    float acc[2][8][4] = {};
    run_gemm(g_inter + (size_t)t0 * KQ, KQ,
             g_w2 + h0, H_DIM,
             KQ / BK, smem, sb, acc);

#pragma unroll
    for (int nf = 0; nf < 8; nf++) {
        const int cn = wc * 64 + nf * 8 + 2 * t4;
        float d0[8], d1[8];
#pragma unroll
        for (int e2 = 0; e2 < 8; e2++) {
            d0[e2] = dsm[e2 * 256 + cn];
            d1[e2] = dsm[e2 * 256 + cn + 1];
        }
#pragma unroll
        for (int mf = 0; mf < 2; mf++) {
#pragma unroll
            for (int hi = 0; hi < 2; hi++) {
                const int r = wr * 32 + mf * 16 + g + hi * 8;
                const float4* rp = (const float4*)(rsm + r * 8);
                const float4 rA = rp[0], rB = rp[1];
                float b0 = rA.x * d0[0] + rA.y * d0[1] + rA.z * d0[2] + rA.w * d0[3]
                         + rB.x * d0[4] + rB.y * d0[5] + rB.z * d0[6] + rB.w * d0[7];
                float b1 = rA.x * d1[0] + rA.y * d1[1] + rA.z * d1[2] + rA.w * d1[3]
                         + rB.x * d1[4] + rB.y * d1[5] + rB.z * d1[6] + rB.w * d1[7];
                float2 v;
                v.x = acc[mf][nf][hi * 2]     + b0;
                v.y = acc[mf][nf][hi * 2 + 1] + b1;
                *(float2*)(out + (size_t)(t0 + r) * H_DIM + h0 + cn) = v;
            }
        }
    }
}

extern "C" void kernel_launch(void* const* d_in, const int* in_sizes, int n_in,
                              void* d_out, int out_size)
{
    const float* hidden  = (const float*)d_in[0];
    const float* routing = (const float*)d_in[1];
    const float* gup     = (const float*)d_in[2];
    const float* gub     = (const float*)d_in[3];
    const float* down    = (const float*)d_in[4];
    const float* dpb     = (const float*)d_in[5];
    float* out = (float*)d_out;

    cudaFuncSetAttribute(k_gemm1, cudaFuncAttributeMaxDynamicSharedMemorySize, SMEM_SZ);
    cudaFuncSetAttribute(k_gemm2, cudaFuncAttributeMaxDynamicSharedMemorySize, SMEM_SZ);

    float *w1, *w2, *hs;
    cudaGetSymbolAddress((void**)&w1, g_w1);
    cudaGetSymbolAddress((void**)&w2, g_w2);
    cudaGetSymbolAddress((void**)&hs, g_hs);

    // pre-round all GEMM operands to tf32-representable fp32 (removes in-loop CVT)
    k_conv<<<(16777216 + 255) / 256, 256>>>((const float4*)gup,    (float4*)w1, 16777216);
    k_conv<<<( 8388608 + 255) / 256, 256>>>((const float4*)down,   (float4*)w2,  8388608);
    k_conv<<<( 1048576 + 255) / 256, 256>>>((const float4*)hidden, (float4*)hs,  1048576);

    dim3 g1(GU_COLS / BN, T_DIM / BM, E_NUM);   // (16, 16, 8)
    k_gemm1<<<g1, NTHR, SMEM_SZ>>>(routing, gub);

    dim3 g2(H_DIM / BN, T_DIM / BM);            // (8, 16)
    k_gemm2<<<g2, NTHR, SMEM_SZ>>>(routing, dpb, out);
}

// round 7
// speedup vs baseline: 3.3810x; 1.0534x over previous
#include <cuda_runtime.h>
#include <cstdint>

// GptOssExperts: out[t,h] = sum_e r[t,e]*(act(hs@gup[e]+gub[e])@dp[e]+dpb[e])
// Legacy mma.sync tf32 path (tcgen05 rejected by toolchain's sm_103 base target).
//  R7: 256 thr / 8 warps of 64x64 (big reg budget), manual fragment double-buffering
//      across k8-steps (load s+1 before mma s), ldmatrix.x4 for A fragments,
//      pre-rounded tf32 operands (no in-loop CVT), BK=32, 3-stage cp.async.

constexpr int T_DIM = 2048, H_DIM = 2048, I_DIM = 2048, E_NUM = 8;
constexpr int GU_COLS = 4096;          // 2*I
constexpr int KQ = E_NUM * I_DIM;      // 16384
constexpr int BM = 128, BN = 256, BK = 32;
constexpr int NTHR = 256;
constexpr int STAGES = 3;

constexpr int A_ROW = 144;             // 32 floats + 16B pad (multiple of 16 for LDSM)
constexpr int B_ROW = 1056;            // 256 floats + 32B pad
constexpr int A_ST = BM * A_ROW;       // 18432
constexpr int B_ST = BK * B_ROW;       // 33792
constexpr int OFF_A = 0;
constexpr int OFF_B = STAGES * A_ST;             // 55296
constexpr int OFF_AUX = OFF_B + STAGES * B_ST;   // 156672
constexpr int SMEM_SZ = OFF_AUX + 12544;         // 169216

// static scratch (device-global; allocation-free)
__device__ float g_w1[67108864];       // tf32-rounded gate_up_proj  (268 MB)
__device__ float g_w2[33554432];       // tf32-rounded down_proj     (134 MB)
__device__ float g_hs[4194304];        // tf32-rounded hidden_states (16 MB)
__device__ float g_inter[33554432];    // routed-scaled intermediate [T][E*I], tf32-rounded

__device__ __forceinline__ uint32_t f2tf32(float x) {
    uint32_t r; asm("cvt.rna.tf32.f32 %0, %1;" : "=r"(r) : "f"(x)); return r;
}
__device__ __forceinline__ uint32_t cvta_smem(const void* p) {
    uint32_t a;
    asm("{ .reg .u64 t; cvta.to.shared.u64 t, %1; cvt.u32.u64 %0, t; }" : "=r"(a) : "l"(p));
    return a;
}
__device__ __forceinline__ void cp16(uint32_t saddr, const void* g) {
    asm volatile("cp.async.cg.shared.global [%0], [%1], 16;" :: "r"(saddr), "l"(g));
}
__device__ __forceinline__ void cp_commit() {
    asm volatile("cp.async.commit_group;" ::);
}
template <int N> __device__ __forceinline__ void cp_wait() {
    asm volatile("cp.async.wait_group %0;" :: "n"(N));
}
__device__ __forceinline__ void mma_tf32(float (&c)[4],
    uint32_t a0, uint32_t a1, uint32_t a2, uint32_t a3, uint32_t b0, uint32_t b1)
{
    asm volatile(
        "mma.sync.aligned.m16n8k8.row.col.f32.tf32.tf32.f32 "
        "{%0,%1,%2,%3}, {%4,%5,%6,%7}, {%8,%9}, {%0,%1,%2,%3};"
        : "+f"(c[0]), "+f"(c[1]), "+f"(c[2]), "+f"(c[3])
        : "r"(a0), "r"(a1), "r"(a2), "r"(a3), "r"(b0), "r"(b1));
}
// ldmatrix.x4 on b16 rows == tf32 m16n8k8 A fragment (tile0=a0,tile1=a1,tile2=a2,tile3=a3)
__device__ __forceinline__ void ldsm4(uint32_t (&r)[4], uint32_t addr) {
    asm volatile("ldmatrix.sync.aligned.m8n8.x4.shared.b16 {%0,%1,%2,%3}, [%4];"
                 : "=r"(r[0]), "=r"(r[1]), "=r"(r[2]), "=r"(r[3]) : "r"(addr));
}

// ---- pre-pass: round fp32 -> tf32-representable fp32 (vectorized) ----
__global__ __launch_bounds__(256) void k_conv(const float4* __restrict__ src,
                                              float4* __restrict__ dst, int n4)
{
    int i = blockIdx.x * 256 + threadIdx.x;
    if (i < n4) {
        float4 v = src[i];
        float4 o;
        o.x = __uint_as_float(f2tf32(v.x));
        o.y = __uint_as_float(f2tf32(v.y));
        o.z = __uint_as_float(f2tf32(v.z));
        o.w = __uint_as_float(f2tf32(v.w));
        dst[i] = o;
    }
}

// ---- fragment load for one k8-step ----
// A via LDSM.x4: lane address = row (wr*64+mf*16 + (l&7)+8*((l>>3)&1)) * A_ROW + (l>>4)*16 + s*32
// B scalar LDS: bank (8t4 + g + C)%32 -> conflict-free
__device__ __forceinline__ void load_frags(uint32_t sA_lane, const char* sB,
    int s, int wc, int g, int t4, uint32_t (&a)[4][4], uint32_t (&b)[8][2])
{
#pragma unroll
    for (int mf = 0; mf < 4; mf++)
        ldsm4(a[mf], sA_lane + mf * 16 * A_ROW + s * 32);
    const char* pb = sB + (s * 8 + t4) * B_ROW + (wc * 64 + g) * 4;
#pragma unroll
    for (int nf = 0; nf < 8; nf++) {
        b[nf][0] = *(const uint32_t*)(pb + nf * 32);
        b[nf][1] = *(const uint32_t*)(pb + nf * 32 + 4 * B_ROW);
    }
}
__device__ __forceinline__ void mma_step(const uint32_t (&a)[4][4],
    const uint32_t (&b)[8][2], float (&acc)[4][8][4])
{
#pragma unroll
    for (int mf = 0; mf < 4; mf++)
#pragma unroll
        for (int nf = 0; nf < 8; nf++)
            mma_tf32(acc[mf][nf], a[mf][0], a[mf][1], a[mf][2], a[mf][3],
                     b[nf][0], b[nf][1]);
}

// ---- one BK=32 slab: 4 k8-steps with in-register double-buffered fragments ----
__device__ __forceinline__ void compute_slab(uint32_t sA_lane, const char* sB,
    int wc, int g, int t4, float (&acc)[4][8][4])
{
    uint32_t a0[4][4], b0[8][2], a1[4][4], b1[8][2];
    load_frags(sA_lane, sB, 0, wc, g, t4, a0, b0);
    load_frags(sA_lane, sB, 1, wc, g, t4, a1, b1);
    mma_step(a0, b0, acc);
    load_frags(sA_lane, sB, 2, wc, g, t4, a0, b0);
    mma_step(a1, b1, acc);
    load_frags(sA_lane, sB, 3, wc, g, t4, a1, b1);
    mma_step(a0, b0, acc);
    mma_step(a1, b1, acc);
}

// ---- cp.async copy of one BK=32 slab (256 threads; compact pointer state) ----
struct Copier { const float *ga0, *gb0; uint32_t sa0, sb0; int lda, ldb; };
__device__ __forceinline__ void init_copier(Copier& c, uint32_t smem_u32,
    const float* __restrict__ A, int lda, const float* __restrict__ B, int ldb)
{
    const int tid = threadIdx.x;
    c.lda = lda; c.ldb = ldb;
    int m = tid >> 3, kq = tid & 7;            // A chunk j: m + 32j
    c.sa0 = smem_u32 + OFF_A + m * A_ROW + kq * 16;
    c.ga0 = A + (size_t)m * lda + kq * 4;
    int k = tid >> 6, nq = tid & 63;           // B chunk j: k + 4j
    c.sb0 = smem_u32 + OFF_B + k * B_ROW + nq * 16;
    c.gb0 = B + (size_t)k * ldb + nq * 4;
}
__device__ __forceinline__ void issue_slab(const Copier& c, int i) {
    const int slot = i % STAGES;
    const size_t ka = (size_t)i * BK;
#pragma unroll
    for (int j = 0; j < 4; j++)                // A: 1024 chunks / 256 thr
        cp16(c.sa0 + slot * A_ST + j * 32 * A_ROW, c.ga0 + ka + (size_t)j * 32 * c.lda);
#pragma unroll
    for (int j = 0; j < 8; j++)                // B: 2048 chunks / 256 thr
        cp16(c.sb0 + slot * B_ST + j * 4 * B_ROW, c.gb0 + (ka + 4 * j) * (size_t)c.ldb);
}

__device__ __forceinline__ void run_gemm(
    const float* __restrict__ A, int lda, const float* __restrict__ B, int ldb,
    int nslab, char* smem, uint32_t smem_u32, float (&acc)[4][8][4])
{
    const int tid = threadIdx.x, lane = tid & 31, wid = tid >> 5;
    const int wr = wid >> 2, wc = wid & 3, g = lane >> 2, t4 = lane & 3;

    // per-lane LDSM base address (within stage-0 A buffer)
    const uint32_t sA_lane0 = smem_u32 + OFF_A
        + (uint32_t)(wr * 64 + (lane & 7) + 8 * ((lane >> 3) & 1)) * A_ROW
        + (uint32_t)(lane >> 4) * 16;

    Copier c; init_copier(c, smem_u32, A, lda, B, ldb);

#pragma unroll
    for (int i = 0; i < STAGES - 1; i++) { issue_slab(c, i); cp_commit(); }

    for (int i = 0; i < nslab; i++) {
        cp_wait<STAGES - 2>();
        __syncthreads();
        if (i + STAGES - 1 < nslab) issue_slab(c, i + STAGES - 1);
        cp_commit();
        const int slot = i % STAGES;
        compute_slab(sA_lane0 + slot * A_ST, smem + OFF_B + slot * B_ST,
                     wc, g, t4, acc);
    }
}

// ================= Stage 1: gu = hs @ gup[e] + gub; GLU; fold routing -> g_inter =================
__global__ __launch_bounds__(NTHR, 1) void k_gemm1(
    const float* __restrict__ routing, const float* __restrict__ gub)
{
    extern __shared__ char smem[];
    const uint32_t sb = cvta_smem(smem);
    const int tid = threadIdx.x, lane = tid & 31, wid = tid >> 5;
    const int wr = wid >> 2, wc = wid & 3, g = lane >> 2, t4 = lane & 3;
    const int e = blockIdx.z, t0 = blockIdx.y * BM, j0 = blockIdx.x * BN;

    float* rs   = (float*)(smem + OFF_AUX);        // [128]
    float* bias = (float*)(smem + OFF_AUX + 512);  // [256]
    if (tid < 128) rs[tid] = routing[(size_t)(t0 + tid) * E_NUM + e];
    bias[tid] = gub[(size_t)e * GU_COLS + j0 + tid];
    __syncthreads();

    float acc[4][8][4] = {};
    run_gemm(g_hs + (size_t)t0 * H_DIM, H_DIM,
             g_w1 + (size_t)e * H_DIM * GU_COLS + j0, GU_COLS,
             H_DIM / BK, smem, sb, acc);

#pragma unroll
    for (int mf = 0; mf < 4; mf++) {
#pragma unroll
        for (int hi = 0; hi < 2; hi++) {
            const int r = wr * 64 + mf * 16 + g + hi * 8;
            const float rv = rs[r];
            float* grow = g_inter + (size_t)(t0 + r) * KQ + (size_t)e * I_DIM + (j0 >> 1);
#pragma unroll
            for (int nf = 0; nf < 8; nf++) {
                const int cn = wc * 64 + nf * 8 + 2 * t4;  // even gu col = gate; +1 = up
                float gate = acc[mf][nf][hi * 2]     + bias[cn];
                float up   = acc[mf][nf][hi * 2 + 1] + bias[cn + 1];
                gate = fminf(gate, 7.0f);
                up   = fminf(fmaxf(up, -7.0f), 7.0f);
                const float glu = gate / (1.0f + __expf(-1.702f * gate));
                grow[cn >> 1] = __uint_as_float(f2tf32((up + 1.0f) * glu * rv));
            }
        }
    }
}

// ================= Stage 2: out = inter'[T,E*I] @ down[E*I,H] + routing @ dpb =================
__global__ __launch_bounds__(NTHR, 1) void k_gemm2(
    const float* __restrict__ routing, const float* __restrict__ dpb,
    float* __restrict__ out)
{
    extern __shared__ char smem[];
    const uint32_t sb = cvta_smem(smem);
    const int tid = threadIdx.x, lane = tid & 31, wid = tid >> 5;
    const int wr = wid >> 2, wc = wid & 3, g = lane >> 2, t4 = lane & 3;
    const int t0 = blockIdx.y * BM, h0 = blockIdx.x * BN;

    float* rsm = (float*)(smem + OFF_AUX);         // [128][8]
    float* dsm = (float*)(smem + OFF_AUX + 4096);  // [8][256]
#pragma unroll
    for (int j = 0; j < 4; j++) {
        int idx = tid + NTHR * j;
        rsm[idx] = routing[(size_t)t0 * E_NUM + idx];
    }
#pragma unroll
    for (int j = 0; j < 8; j++) {
        int idx = tid + NTHR * j;
        dsm[idx] = dpb[(size_t)(idx >> 8) * H_DIM + h0 + (idx & 255)];
    }
    __syncthreads();

    float acc[4][8][4] = {};
    run_gemm(g_inter + (size_t)t0 * KQ, KQ,
             g_w2 + h0, H_DIM,
             KQ / BK, smem, sb, acc);

#pragma unroll
    for (int nf = 0; nf < 8; nf++) {
        const int cn = wc * 64 + nf * 8 + 2 * t4;
        float d0[8], d1[8];
#pragma unroll
        for (int e2 = 0; e2 < 8; e2++) {
            d0[e2] = dsm[e2 * 256 + cn];
            d1[e2] = dsm[e2 * 256 + cn + 1];
        }
#pragma unroll
        for (int mf = 0; mf < 4; mf++) {
#pragma unroll
            for (int hi = 0; hi < 2; hi++) {
                const int r = wr * 64 + mf * 16 + g + hi * 8;
                const float4* rp = (const float4*)(rsm + r * 8);
                const float4 rA = rp[0], rB = rp[1];
                float b0 = rA.x * d0[0] + rA.y * d0[1] + rA.z * d0[2] + rA.w * d0[3]
                         + rB.x * d0[4] + rB.y * d0[5] + rB.z * d0[6] + rB.w * d0[7];
                float b1 = rA.x * d1[0] + rA.y * d1[1] + rA.z * d1[2] + rA.w * d1[3]
                         + rB.x * d1[4] + rB.y * d1[5] + rB.z * d1[6] + rB.w * d1[7];
                float2 v;
                v.x = acc[mf][nf][hi * 2]     + b0;
                v.y = acc[mf][nf][hi * 2 + 1] + b1;
                *(float2*)(out + (size_t)(t0 + r) * H_DIM + h0 + cn) = v;
            }
        }
    }
}

extern "C" void kernel_launch(void* const* d_in, const int* in_sizes, int n_in,
                              void* d_out, int out_size)
{
    const float* hidden  = (const float*)d_in[0];
    const float* routing = (const float*)d_in[1];
    const float* gup     = (const float*)d_in[2];
    const float* gub     = (const float*)d_in[3];
    const float* down    = (const float*)d_in[4];
    const float* dpb     = (const float*)d_in[5];
    float* out = (float*)d_out;

    cudaFuncSetAttribute(k_gemm1, cudaFuncAttributeMaxDynamicSharedMemorySize, SMEM_SZ);
    cudaFuncSetAttribute(k_gemm2, cudaFuncAttributeMaxDynamicSharedMemorySize, SMEM_SZ);

    float *w1, *w2, *hs;
    cudaGetSymbolAddress((void**)&w1, g_w1);
    cudaGetSymbolAddress((void**)&w2, g_w2);
    cudaGetSymbolAddress((void**)&hs, g_hs);

    // pre-round all GEMM operands to tf32-representable fp32 (removes in-loop CVT)
    k_conv<<<(16777216 + 255) / 256, 256>>>((const float4*)gup,    (float4*)w1, 16777216);
    k_conv<<<( 8388608 + 255) / 256, 256>>>((const float4*)down,   (float4*)w2,  8388608);
    k_conv<<<( 1048576 + 255) / 256, 256>>>((const float4*)hidden, (float4*)hs,  1048576);

    dim3 g1(GU_COLS / BN, T_DIM / BM, E_NUM);   // (16, 16, 8)
    k_gemm1<<<g1, NTHR, SMEM_SZ>>>(routing, gub);

    dim3 g2(H_DIM / BN, T_DIM / BM);            // (8, 16)
    k_gemm2<<<g2, NTHR, SMEM_SZ>>>(routing, dpb, out);
}